// round 1
// baseline (speedup 1.0000x reference)
#include <cuda_runtime.h>
#include <math.h>

#define BATCH 256
#define TLEN  512
#define CIN0  271
#define CH    320
#define NSUBJ 4
#define EPSV  1e-5f

#define TILE_T  128
#define TILE_CO 64
#define KC      8
#define NTH     256

// Scratch (allocation-free rule: __device__ globals)
__device__ float g_bufA[(size_t)BATCH * CH * TLEN];   // 167.8 MB
__device__ float g_bufB[(size_t)BATCH * CH * TLEN];   // 167.8 MB
__device__ float g_wt[3 * CH * CH];                   // transposed weights [tap][ci][co]
__device__ float g_sum[NSUBJ * CH];
__device__ float g_sumsq[NSUBJ * CH];
__device__ float g_scale[NSUBJ * CH];
__device__ float g_shift[NSUBJ * CH];
__device__ int   g_cnt[NSUBJ];

__device__ __forceinline__ float gelu_f(float x) {
    // exact erf GELU (matches jax.nn.gelu approximate=False / torch F.gelu)
    return 0.5f * x * (1.0f + erff(x * 0.7071067811865475f));
}

// ---------------------------------------------------------------------------
// Per-subject batch counts (one block of 256 threads, one thread per batch elem)
// ---------------------------------------------------------------------------
__global__ void count_kernel(const int* __restrict__ subj) {
    __shared__ int c[NSUBJ];
    int tid = threadIdx.x;
    if (tid < NSUBJ) c[tid] = 0;
    __syncthreads();
    atomicAdd(&c[subj[tid]], 1);
    __syncthreads();
    if (tid < NSUBJ) g_cnt[tid] = c[tid];
}

__global__ void zero_stats_kernel() {
    int i = blockIdx.x * blockDim.x + threadIdx.x;
    if (i < NSUBJ * CH) { g_sum[i] = 0.f; g_sumsq[i] = 0.f; }
}

// w: [CH][cin][3] row-major  ->  g_wt: [tap][cin][CH]
__global__ void transpose_w_kernel(const float* __restrict__ w, int cin) {
    int i = blockIdx.x * blockDim.x + threadIdx.x;
    int n = CH * cin * 3;
    if (i >= n) return;
    int tap = i % 3;
    int ci  = (i / 3) % cin;
    int co  = i / (3 * cin);
    g_wt[((size_t)tap * cin + ci) * CH + co] = w[i];
}

// ---------------------------------------------------------------------------
// Conv1d (K=3, SAME) implicit GEMM. One block: 64 co x 128 t for one batch b.
// Optionally adds residual (input at same [co][t]). Accumulates per-subject
// per-channel sum/sumsq of the OUTPUT (pre-BN) via warp reduce + atomics.
// ---------------------------------------------------------------------------
template <int CIN, bool RES>
__global__ void __launch_bounds__(NTH) conv_kernel(
    const float* __restrict__ in,      // [BATCH][CIN][TLEN]
    const float* __restrict__ bias,    // [CH]
    const int*   __restrict__ subj,    // [BATCH]
    float*       __restrict__ out)     // [BATCH][CH][TLEN]
{
    __shared__ float Ws[3][KC][TILE_CO];
    __shared__ float Xs[KC][TILE_T + 2];

    const int b     = blockIdx.z;
    const int coBlk = blockIdx.y * TILE_CO;
    const int tBlk  = blockIdx.x * TILE_T;
    const int tid   = threadIdx.x;
    const int co0   = (tid >> 5) * 8;   // 8 warps -> 8 co-groups of 8
    const int t0    = (tid & 31) * 4;   // 32 lanes -> 128 t positions

    const float* inB = in + (size_t)b * CIN * TLEN;

    float acc[8][4];
#pragma unroll
    for (int r = 0; r < 8; r++)
#pragma unroll
        for (int j = 0; j < 4; j++) acc[r][j] = 0.f;

    for (int c0 = 0; c0 < CIN; c0 += KC) {
        __syncthreads();
        // Weights: g_wt[(tap*CIN + cig)*CH + coBlk + co] — coalesced in co.
#pragma unroll
        for (int i = tid; i < 3 * KC * TILE_CO; i += NTH) {   // 6 iterations
            int co  = i & (TILE_CO - 1);
            int r   = i >> 6;
            int ci  = r & (KC - 1);
            int tap = r >> 3;
            int cig = c0 + ci;
            Ws[tap][ci][co] = (cig < CIN)
                ? g_wt[((size_t)tap * CIN + cig) * CH + coBlk + co] : 0.f;
        }
        // Input tile with halo: Xs[ci][tt] = in[b][cig][tBlk + tt - 1], zero-padded.
        for (int i = tid; i < KC * (TILE_T + 2); i += NTH) {
            int ci = i / (TILE_T + 2);
            int tt = i - ci * (TILE_T + 2);
            int gt = tBlk + tt - 1;
            int cig = c0 + ci;
            float v = 0.f;
            if (cig < CIN && (unsigned)gt < (unsigned)TLEN)
                v = inB[(size_t)cig * TLEN + gt];
            Xs[ci][tt] = v;
        }
        __syncthreads();

#pragma unroll
        for (int ci = 0; ci < KC; ci++) {
            float xv[6];
#pragma unroll
            for (int j = 0; j < 6; j++) xv[j] = Xs[ci][t0 + j];
#pragma unroll
            for (int tap = 0; tap < 3; tap++) {
                float wv[8];
#pragma unroll
                for (int r = 0; r < 8; r++) wv[r] = Ws[tap][ci][co0 + r];
#pragma unroll
                for (int r = 0; r < 8; r++)
#pragma unroll
                    for (int j = 0; j < 4; j++)
                        acc[r][j] = fmaf(wv[r], xv[j + tap], acc[r][j]);
            }
        }
    }

    // Epilogue: bias (+ residual), store, and stats accumulation.
    const int s = subj[b];
    float* outB = out + ((size_t)b * CH + coBlk) * TLEN + tBlk;
    const float* resB = in + ((size_t)b * CH + coBlk) * TLEN + tBlk; // valid only if RES

    float ssum[8], ssq[8];
#pragma unroll
    for (int r = 0; r < 8; r++) {
        float bv = bias[coBlk + co0 + r];
        float4 res4 = make_float4(0.f, 0.f, 0.f, 0.f);
        if (RES)
            res4 = *(const float4*)(resB + (size_t)(co0 + r) * TLEN + t0);
        float v0 = acc[r][0] + bv;
        float v1 = acc[r][1] + bv;
        float v2 = acc[r][2] + bv;
        float v3 = acc[r][3] + bv;
        if (RES) { v0 += res4.x; v1 += res4.y; v2 += res4.z; v3 += res4.w; }
        *(float4*)(outB + (size_t)(co0 + r) * TLEN + t0) = make_float4(v0, v1, v2, v3);
        ssum[r] = v0 + v1 + v2 + v3;
        ssq[r]  = v0 * v0 + v1 * v1 + v2 * v2 + v3 * v3;
    }
    // Warp lanes span t only (same co rows) -> shuffle reduce then 16 atomics/warp.
#pragma unroll
    for (int off = 16; off; off >>= 1) {
#pragma unroll
        for (int r = 0; r < 8; r++) {
            ssum[r] += __shfl_down_sync(0xffffffffu, ssum[r], off);
            ssq[r]  += __shfl_down_sync(0xffffffffu, ssq[r],  off);
        }
    }
    if ((tid & 31) == 0) {
#pragma unroll
        for (int r = 0; r < 8; r++) {
            atomicAdd(&g_sum[s * CH + coBlk + co0 + r],   ssum[r]);
            atomicAdd(&g_sumsq[s * CH + coBlk + co0 + r], ssq[r]);
        }
    }
}

__global__ void finalize_kernel(const float* __restrict__ gamma,
                                const float* __restrict__ beta) {
    int i = blockIdx.x * blockDim.x + threadIdx.x;
    if (i >= NSUBJ * CH) return;
    int s = i / CH;
    float cnt  = fmaxf((float)g_cnt[s] * (float)TLEN, 1.0f);
    float mean = g_sum[i] / cnt;
    float var  = g_sumsq[i] / cnt - mean * mean;
    float sc   = gamma[i] * rsqrtf(var + EPSV);
    g_scale[i] = sc;
    g_shift[i] = beta[i] - mean * sc;
}

// dst[i] = gelu(src[i]*scale + shift), float4-vectorized; src==dst allowed.
__global__ void bn_gelu_kernel(const float* __restrict__ src,
                               float* __restrict__ dst,
                               const int* __restrict__ subj) {
    size_t idx = (size_t)blockIdx.x * blockDim.x + threadIdx.x;
    size_t n4 = (size_t)BATCH * CH * TLEN / 4;
    if (idx >= n4) return;
    size_t e = idx * 4;
    int b = (int)(e / ((size_t)CH * TLEN));
    int c = (int)((e / TLEN) % CH);
    int s = subj[b];
    float sc = g_scale[s * CH + c];
    float sh = g_shift[s * CH + c];
    float4 v = ((const float4*)src)[idx];
    v.x = gelu_f(fmaf(v.x, sc, sh));
    v.y = gelu_f(fmaf(v.y, sc, sh));
    v.z = gelu_f(fmaf(v.z, sc, sh));
    v.w = gelu_f(fmaf(v.w, sc, sh));
    ((float4*)dst)[idx] = v;
}

// ---------------------------------------------------------------------------
extern "C" void kernel_launch(void* const* d_in, const int* in_sizes, int n_in,
                              void* d_out, int out_size) {
    const float* X    = (const float*)d_in[0];
    const int*   subj = (const int*)  d_in[1];
    const float* w0   = (const float*)d_in[2];
    const float* b0   = (const float*)d_in[3];
    const float* w1   = (const float*)d_in[4];
    const float* b1   = (const float*)d_in[5];
    const float* w2   = (const float*)d_in[6];
    const float* b2   = (const float*)d_in[7];
    const float* g0   = (const float*)d_in[8];
    const float* be0  = (const float*)d_in[9];
    const float* g1   = (const float*)d_in[10];
    const float* be1  = (const float*)d_in[11];
    const float* g2   = (const float*)d_in[12];
    const float* be2  = (const float*)d_in[13];
    float* out = (float*)d_out;
    (void)in_sizes; (void)n_in; (void)out_size;

    float *pA, *pB;
    cudaGetSymbolAddress((void**)&pA, g_bufA);
    cudaGetSymbolAddress((void**)&pB, g_bufB);

    dim3 cgrid(TLEN / TILE_T, CH / TILE_CO, BATCH);   // (4, 5, 256)
    const int sgrid = (NSUBJ * CH + 255) / 256;
    const size_t n4 = (size_t)BATCH * CH * TLEN / 4;
    const int tgrid = (int)((n4 + 255) / 256);

    count_kernel<<<1, BATCH>>>(subj);

    // Layer 0: conv0(X) -> Y0(bufA); stats; G0 = gelu(bn(Y0)) in place.
    transpose_w_kernel<<<(CH * CIN0 * 3 + 255) / 256, 256>>>(w0, CIN0);
    zero_stats_kernel<<<sgrid, 256>>>();
    conv_kernel<CIN0, false><<<cgrid, NTH>>>(X, b0, subj, pA);
    finalize_kernel<<<sgrid, 256>>>(g0, be0);
    bn_gelu_kernel<<<tgrid, 256>>>(pA, pA, subj);

    // Layer 1: Y1 = conv1(G0) + G0 -> bufB; stats; G1 in place.
    transpose_w_kernel<<<(CH * CH * 3 + 255) / 256, 256>>>(w1, CH);
    zero_stats_kernel<<<sgrid, 256>>>();
    conv_kernel<CH, true><<<cgrid, NTH>>>(pA, b1, subj, pB);
    finalize_kernel<<<sgrid, 256>>>(g1, be1);
    bn_gelu_kernel<<<tgrid, 256>>>(pB, pB, subj);

    // Layer 2: Y2 = conv2(G1) + G1 -> bufA; stats; final gelu(bn) -> d_out.
    transpose_w_kernel<<<(CH * CH * 3 + 255) / 256, 256>>>(w2, CH);
    zero_stats_kernel<<<sgrid, 256>>>();
    conv_kernel<CH, true><<<cgrid, NTH>>>(pB, b2, subj, pA);
    finalize_kernel<<<sgrid, 256>>>(g2, be2);
    bn_gelu_kernel<<<tgrid, 256>>>(pA, out, subj);
}